// round 14
// baseline (speedup 1.0000x reference)
#include <cuda_runtime.h>
#include <cuda_fp16.h>
#include <math.h>
#include <stdint.h>

// Problem constants (fixed shapes)
#define NTOK   8192        // B*S
#define DMODEL 1024
#define NEXP   32
#define ESIZE  256
#define TOPK   4

#define MAX_TILES 544      // sum_e ceil(cnt_e/64) <= 32768/64 + 32

// ---------------- scratch (device globals) ----------------
__device__ int    g_counts[NEXP];
__device__ int    g_toklist[NEXP][NTOK];             // packed token*4 + slot
__device__ float  g_gate[NTOK * TOPK];
__device__ int    g_tiles[MAX_TILES];                // (e << 16) | m_block
__device__ int    g_ntiles;
__device__ __half g_xh[(size_t)NTOK * DMODEL];                 // fp16 x (from route)
__device__ __half g_keysH[(size_t)NEXP * DMODEL * ESIZE];      // fp16 keys [e][d][h]
__device__ __half g_valuesH[(size_t)NEXP * ESIZE * DMODEL];    // fp16 values [e][h][v]
__device__ __half g_Hh[(size_t)NTOK * TOPK * ESIZE];           // fp16 H rows
__device__ __half g_Yph[(size_t)NTOK * TOPK * DMODEL];         // fp16 partial y

__device__ __forceinline__ uint32_t smem_u32(const void* p) {
    uint32_t a;
    asm("{ .reg .u64 t; cvta.to.shared.u64 t, %1; cvt.u32.u64 %0, t; }" : "=r"(a) : "l"(p));
    return a;
}
#define CP_ASYNC16(dst, src) \
    asm volatile("cp.async.cg.shared.global [%0], [%1], 16;" :: "r"(dst), "l"(src))
#define CP_COMMIT() asm volatile("cp.async.commit_group;" ::: "memory")
#define CP_WAIT2()  asm volatile("cp.async.wait_group 2;" ::: "memory")
// streaming (evict-first) global access
#define STCS32(ptr, v) \
    asm volatile("st.global.cs.b32 [%0], %1;" :: "l"(ptr), "r"(v))
#define LDCS128(r0, r1, r2, r3, ptr) \
    asm volatile("ld.global.cs.v4.u32 {%0,%1,%2,%3}, [%4];" \
                 : "=r"(r0), "=r"(r1), "=r"(r2), "=r"(r3) : "l"(ptr))
#define STCS128(ptr, r0, r1, r2, r3) \
    asm volatile("st.global.cs.v4.b32 [%0], {%1,%2,%3,%4};" \
                 :: "l"(ptr), "r"(r0), "r"(r1), "r"(r2), "r"(r3))

// ---------------- kernel 0: zero counts ----------------
__global__ void zero_counts_kernel() {
    if (threadIdx.x < NEXP) g_counts[threadIdx.x] = 0;
}

// ---------------- routing + x->fp16 (1 warp per token; R7-proven) ----------------
__global__ __launch_bounds__(256) void route_kernel(const float* __restrict__ x,
                                                    const float* __restrict__ esel) {
    const int gw   = blockIdx.x * 8 + (threadIdx.x >> 5);
    const int lane = threadIdx.x & 31;

    const float* xr = x + (size_t)gw * DMODEL;
    float4 xreg[8];
#pragma unroll
    for (int j = 0; j < 8; j++) xreg[j] = *(const float4*)(xr + lane * 4 + j * 128);

#pragma unroll
    for (int j = 0; j < 8; j++) {
        __half2 h0 = __floats2half2_rn(xreg[j].x, xreg[j].y);
        __half2 h1 = __floats2half2_rn(xreg[j].z, xreg[j].w);
        uint2 o; o.x = *(uint32_t*)&h0; o.y = *(uint32_t*)&h1;
        *(uint2*)(g_xh + (size_t)gw * DMODEL + lane * 4 + j * 128) = o;
    }

    float myv = -INFINITY;
#pragma unroll 1
    for (int e = 0; e < NEXP; e++) {
        const float* w = esel + (size_t)e * DMODEL;
        float acc = 0.f;
#pragma unroll
        for (int j = 0; j < 8; j++) {
            float4 wv = *(const float4*)(w + lane * 4 + j * 128);
            acc += xreg[j].x * wv.x + xreg[j].y * wv.y + xreg[j].z * wv.z + xreg[j].w * wv.w;
        }
#pragma unroll
        for (int off = 16; off; off >>= 1) acc += __shfl_xor_sync(0xffffffffu, acc, off);
        if (lane == e) myv = acc;
    }

    float v = myv;
#pragma unroll
    for (int k = 0; k < TOPK; k++) {
        float bv = v; int bi = lane;
#pragma unroll
        for (int off = 16; off; off >>= 1) {
            float ov = __shfl_xor_sync(0xffffffffu, bv, off);
            int   oi = __shfl_xor_sync(0xffffffffu, bi, off);
            if (ov > bv || (ov == bv && oi < bi)) { bv = ov; bi = oi; }
        }
        if (lane == 0) {
            float g = 1.f / (1.f + expf(-bv));
            g_gate[gw * TOPK + k] = g;
            int pos = atomicAdd(&g_counts[bi], 1);
            g_toklist[bi][pos] = gw * TOPK + k;
        }
        if (lane == bi) v = -INFINITY;
    }
}

// ---------------- elementwise f32 -> f16 convert ----------------
__global__ __launch_bounds__(256) void convert_h_kernel(const float* __restrict__ in,
                                                        __half* __restrict__ out) {
    const int idx = blockIdx.x * 256 + threadIdx.x;
    const float4* p = (const float4*)in;
    float4 a = p[idx * 2], b = p[idx * 2 + 1];
    __half2 h0 = __floats2half2_rn(a.x, a.y);
    __half2 h1 = __floats2half2_rn(a.z, a.w);
    __half2 h2 = __floats2half2_rn(b.x, b.y);
    __half2 h3 = __floats2half2_rn(b.z, b.w);
    uint4 o;
    o.x = *(uint32_t*)&h0; o.y = *(uint32_t*)&h1;
    o.z = *(uint32_t*)&h2; o.w = *(uint32_t*)&h3;
    ((uint4*)out)[idx] = o;
}

// ---------------- build compacted tile list (1 warp) ----------------
__global__ void build_tiles_kernel() {
    const int lane = threadIdx.x;
    int cnt = g_counts[lane];
    int nt  = (cnt + 63) >> 6;                // ceil(cnt/64), BM=64
    int off = nt;
#pragma unroll
    for (int d = 1; d < 32; d <<= 1) {
        int o = __shfl_up_sync(0xffffffffu, off, d);
        if (lane >= d) off += o;
    }
    int excl = off - nt;
    if (lane == 31) g_ntiles = off;
    for (int i = 0; i < nt; i++)
        g_tiles[excl + i] = (lane << 16) | i;
}

// ---------------- HMMA fp16 GEMM: BM=64, BN=256, BK=32, 8 warps ------------------
// IS_G1: A=g_xh (K=1024), B=keys, 32 iters, 1 n-block, epi relu*gate->g_Hh.
// else : A=g_Hh (K=256),  B=values, 32 iters covering ALL 4 n-blocks (N=1024),
//        continuous pipeline across nb boundaries, epi flush (streaming) at s&7==7.
#define ASTRIDE 40    // halves per A smem row (80B)
#define BSTRIDE 264   // halves per B smem row (528B): conflict-free trans ldmatrix
#define NSTAGE  4
#define A_ST_BYTES (64 * ASTRIDE * 2)    // 5120
#define B_ST_BYTES (32 * BSTRIDE * 2)    // 16896
#define SM_OFF_A   1024
#define SM_OFF_B   (SM_OFF_A + NSTAGE * A_ST_BYTES)
#define SM_TOTAL   (SM_OFF_B + NSTAGE * B_ST_BYTES)   // 89088

__device__ __forceinline__ void ldsm_x4(uint32_t (&r)[4], uint32_t addr) {
    asm volatile("ldmatrix.sync.aligned.m8n8.x4.shared.b16 {%0,%1,%2,%3}, [%4];"
                 : "=r"(r[0]), "=r"(r[1]), "=r"(r[2]), "=r"(r[3]) : "r"(addr));
}
__device__ __forceinline__ void ldsm_x4_trans(uint32_t (&r)[4], uint32_t addr) {
    asm volatile("ldmatrix.sync.aligned.m8n8.x4.trans.shared.b16 {%0,%1,%2,%3}, [%4];"
                 : "=r"(r[0]), "=r"(r[1]), "=r"(r[2]), "=r"(r[3]) : "r"(addr));
}
__device__ __forceinline__ void mma16816(float (&c)[4], const uint32_t (&a)[4],
                                         uint32_t b0, uint32_t b1) {
    asm volatile(
        "mma.sync.aligned.m16n8k16.row.col.f32.f16.f16.f32 "
        "{%0,%1,%2,%3}, {%4,%5,%6,%7}, {%8,%9}, {%0,%1,%2,%3};"
        : "+f"(c[0]), "+f"(c[1]), "+f"(c[2]), "+f"(c[3])
        : "r"(a[0]), "r"(a[1]), "r"(a[2]), "r"(a[3]), "r"(b0), "r"(b1));
}

template <bool IS_G1>
__global__ __launch_bounds__(256, 2) void moe_hmma_kernel() {
    extern __shared__ char smem[];
    if (blockIdx.y >= (unsigned)g_ntiles) return;
    const int tile = g_tiles[blockIdx.y];
    const int e    = tile >> 16;
    const int m0   = (tile & 0xffff) * 64;
    const int cnt  = g_counts[e];

    int*   sPacked = (int*)(smem);
    float* sGate   = (float*)(smem + 256);

    const int tid    = threadIdx.x;
    const int lane   = tid & 31;
    const int wid    = tid >> 5;
    const int warp_m = wid & 1;      // 0..1 -> 32 rows each
    const int warp_n = wid >> 1;     // 0..3 -> 64 cols each

    if (tid < 64) {
        int m = m0 + tid;
        int p = (m < cnt) ? g_toklist[e][m] : -1;
        sPacked[tid] = p;
        sGate[tid]   = (IS_G1 && p >= 0) ? g_gate[p] : 0.f;
    }
    __syncthreads();

    const int KDIM = IS_G1 ? DMODEL : ESIZE;
    const int N_LD = IS_G1 ? ESIZE : DMODEL;

    const int arow = tid >> 2;
    const int ac   = tid & 3;
    const int apk  = sPacked[arow];
    const __half* Arow = (apk >= 0)
        ? (IS_G1 ? (g_xh + (size_t)(apk >> 2) * KDIM) : (g_Hh + (size_t)apk * KDIM))
        : (IS_G1 ? g_xh : g_Hh);               // dummy valid row; epilogue skips
    const __half* Bsrc = (IS_G1 ? g_keysH : g_valuesH) + (size_t)e * KDIM * N_LD;

    const uint32_t sb = smem_u32(smem);

    auto issue_stage = [&](int s) {
        const int st  = s % NSTAGE;
        const int k0  = IS_G1 ? (s * 32) : ((s & 7) * 32);
        const int n0s = IS_G1 ? 0 : ((s >> 3) * 256);
        uint32_t ad = sb + SM_OFF_A + st * A_ST_BYTES + arow * (ASTRIDE * 2);
        CP_ASYNC16(ad + ac * 16, Arow + k0 + ac * 8);
        uint32_t bd = sb + SM_OFF_B + st * B_ST_BYTES;
#pragma unroll
        for (int j = 0; j < 4; j++) {
            int idx = tid + 256 * j;
            int row = idx >> 5, c16 = idx & 31;
            CP_ASYNC16(bd + row * (BSTRIDE * 2) + c16 * 16,
                       Bsrc + (size_t)(k0 + row) * N_LD + n0s + c16 * 8);
        }
        CP_COMMIT();
    };

    const int S = 32;
#pragma unroll
    for (int p = 0; p < NSTAGE - 1; p++) issue_stage(p);

    float c[2][8][4];
#pragma unroll
    for (int i = 0; i < 2; i++)
#pragma unroll
        for (int j = 0; j < 8; j++)
#pragma unroll
            for (int k = 0; k < 4; k++) c[i][j][k] = 0.f;

    const int lr = lane & 15;
    const int lh = (lane >> 4) * 8;
    const int erow = lane >> 2;
    const int ecol = (lane & 3) * 2;

#pragma unroll 1
    for (int s = 0; s < S; s++) {
        CP_WAIT2();
        __syncthreads();
        if (s + NSTAGE - 1 < S) issue_stage(s + NSTAGE - 1);
        else CP_COMMIT();

        const int st = s % NSTAGE;
        const uint32_t sA = sb + SM_OFF_A + st * A_ST_BYTES;
        const uint32_t sB = sb + SM_OFF_B + st * B_ST_BYTES;
#pragma unroll
        for (int kk = 0; kk < 32; kk += 16) {
            uint32_t a[2][4];
#pragma unroll
            for (int mt = 0; mt < 2; mt++)
                ldsm_x4(a[mt], sA + ((warp_m * 32 + mt * 16 + lr) * ASTRIDE + kk + lh) * 2);
            uint32_t bt[4][4];
#pragma unroll
            for (int g = 0; g < 4; g++)
                ldsm_x4_trans(bt[g], sB + ((kk + lr) * BSTRIDE + warp_n * 64 + g * 16 + lh) * 2);
#pragma unroll
            for (int mt = 0; mt < 2; mt++)
#pragma unroll
                for (int nt = 0; nt < 8; nt++)
                    mma16816(c[mt][nt], a[mt],
                             bt[nt >> 1][2 * (nt & 1)], bt[nt >> 1][2 * (nt & 1) + 1]);
        }

        if (!IS_G1 && (s & 7) == 7) {
            // flush this n-block's accumulators to Yph (streaming stores), reset
            const int n0c = (s >> 3) * 256;
#pragma unroll
            for (int mt = 0; mt < 2; mt++) {
#pragma unroll
                for (int h = 0; h < 2; h++) {
                    int ml = warp_m * 32 + mt * 16 + erow + h * 8;
                    int packed = sPacked[ml];
                    if (packed >= 0) {
                        __half* dst = g_Yph + (size_t)packed * DMODEL + n0c + warp_n * 64 + ecol;
#pragma unroll
                        for (int nt = 0; nt < 8; nt++) {
                            __half2 hv = __floats2half2_rn(c[mt][nt][2 * h + 0],
                                                           c[mt][nt][2 * h + 1]);
                            STCS32(dst + nt * 8, *(uint32_t*)&hv);
                        }
                    }
                }
            }
#pragma unroll
            for (int i = 0; i < 2; i++)
#pragma unroll
                for (int j = 0; j < 8; j++)
#pragma unroll
                    for (int k = 0; k < 4; k++) c[i][j][k] = 0.f;
        }
        // no trailing sync: buffer reuse distance is NSTAGE-1 stages; the top
        // __syncthreads of the next iteration orders reads before the overwrite.
    }

    if (IS_G1) {
#pragma unroll
        for (int mt = 0; mt < 2; mt++) {
#pragma unroll
            for (int h = 0; h < 2; h++) {
                int ml = warp_m * 32 + mt * 16 + erow + h * 8;
                int packed = sPacked[ml];
                if (packed < 0) continue;
                float gate = sGate[ml];
                __half* dst = g_Hh + (size_t)packed * ESIZE + warp_n * 64 + ecol;
#pragma unroll
                for (int nt = 0; nt < 8; nt++) {
                    float f0 = fmaxf(c[mt][nt][2 * h + 0], 0.f) * gate;
                    float f1 = fmaxf(c[mt][nt][2 * h + 1], 0.f) * gate;
                    *(__half2*)(dst + nt * 8) = __floats2half2_rn(f0, f1);
                }
            }
        }
    }
}

// ---------------- reduce: y[t] = sum_slot Yph[t*4+slot] (fp32 accumulate) --------
__global__ __launch_bounds__(256) void reduce_kernel(float* __restrict__ y) {
    int idx = blockIdx.x * blockDim.x + threadIdx.x;
    if (idx >= NTOK * (DMODEL / 8)) return;
    int t  = idx >> 7;
    int d8 = idx & 127;
    float acc[8];
#pragma unroll
    for (int i = 0; i < 8; i++) acc[i] = 0.f;
#pragma unroll
    for (int sl = 0; sl < TOPK; sl++) {
        const __half* src = g_Yph + ((size_t)(t * TOPK + sl)) * DMODEL + d8 * 8;
        uint32_t r0, r1, r2, r3;
        LDCS128(r0, r1, r2, r3, src);
        uint32_t rr[4] = {r0, r1, r2, r3};
#pragma unroll
        for (int i = 0; i < 4; i++) {
            float2 f = __half22float2(*(__half2*)&rr[i]);
            acc[i * 2 + 0] += f.x;
            acc[i * 2 + 1] += f.y;
        }
    }
    float* out = y + (size_t)t * DMODEL + d8 * 8;
    STCS128(out,     __float_as_uint(acc[0]), __float_as_uint(acc[1]),
                     __float_as_uint(acc[2]), __float_as_uint(acc[3]));
    STCS128(out + 4, __float_as_uint(acc[4]), __float_as_uint(acc[5]),
                     __float_as_uint(acc[6]), __float_as_uint(acc[7]));
}

// ---------------- launch: fork/join DAG over 3 streams ----------------
extern "C" void kernel_launch(void* const* d_in, const int* in_sizes, int n_in,
                              void* d_out, int out_size) {
    const float* x      = (const float*)d_in[0];
    const float* keys   = (const float*)d_in[1];
    const float* values = (const float*)d_in[2];
    const float* esel   = (const float*)d_in[3];
    float*       y      = (float*)d_out;

    static cudaStream_t s2 = nullptr, s3 = nullptr;
    static cudaEvent_t evRoot = nullptr, evK = nullptr, evV = nullptr;
    static bool inited = false;
    if (!inited) {
        cudaStreamCreateWithFlags(&s2, cudaStreamNonBlocking);
        cudaStreamCreateWithFlags(&s3, cudaStreamNonBlocking);
        cudaEventCreateWithFlags(&evRoot, cudaEventDisableTiming);
        cudaEventCreateWithFlags(&evK,    cudaEventDisableTiming);
        cudaEventCreateWithFlags(&evV,    cudaEventDisableTiming);
        cudaFuncSetAttribute(moe_hmma_kernel<true>,
                             cudaFuncAttributeMaxDynamicSharedMemorySize, SM_TOTAL);
        cudaFuncSetAttribute(moe_hmma_kernel<false>,
                             cudaFuncAttributeMaxDynamicSharedMemorySize, SM_TOTAL);
        inited = true;
    }

    const int wn8blocks = NEXP * DMODEL * ESIZE / 8 / 256;   // 4096

    // fork
    zero_counts_kernel<<<1, 32>>>();
    cudaEventRecord(evRoot, 0);
    cudaStreamWaitEvent(s2, evRoot, 0);
    cudaStreamWaitEvent(s3, evRoot, 0);

    // main: route -> tiles ; s2: keys convert ; s3: values convert
    route_kernel<<<NTOK / 8, 256>>>(x, esel);
    build_tiles_kernel<<<1, 32>>>();

    __half* keysH_p;   cudaGetSymbolAddress((void**)&keysH_p, g_keysH);
    __half* valuesH_p; cudaGetSymbolAddress((void**)&valuesH_p, g_valuesH);
    convert_h_kernel<<<wn8blocks, 256, 0, s2>>>(keys,   keysH_p);
    convert_h_kernel<<<wn8blocks, 256, 0, s3>>>(values, valuesH_p);
    cudaEventRecord(evK, s2);
    cudaEventRecord(evV, s3);

    // join keys before GEMM1
    cudaStreamWaitEvent(0, evK, 0);
    dim3 g1(1, MAX_TILES, 1);
    moe_hmma_kernel<true><<<g1, 256, SM_TOTAL>>>();

    // join values before GEMM2
    cudaStreamWaitEvent(0, evV, 0);
    dim3 g2(1, MAX_TILES, 1);
    moe_hmma_kernel<false><<<g2, 256, SM_TOTAL>>>();

    reduce_kernel<<<(NTOK * (DMODEL / 8) + 255) / 256, 256>>>(y);
}

// round 15
// speedup vs baseline: 1.0716x; 1.0716x over previous
#include <cuda_runtime.h>
#include <cuda_fp16.h>
#include <math.h>
#include <stdint.h>

// Problem constants (fixed shapes)
#define NTOK   8192        // B*S
#define DMODEL 1024
#define NEXP   32
#define ESIZE  256
#define TOPK   4

#define MAX_TILES 544      // sum_e ceil(cnt_e/64) <= 32768/64 + 32

// ---------------- scratch (device globals) ----------------
__device__ int    g_counts[NEXP];
__device__ int    g_toklist[NEXP][NTOK];             // packed token*4 + slot
__device__ float  g_gate[NTOK * TOPK];
__device__ int    g_tiles[MAX_TILES];                // (e << 16) | m_block
__device__ int    g_ntiles;
__device__ __half g_xh[(size_t)NTOK * DMODEL];                 // fp16 x (from route)
__device__ __half g_keysH[(size_t)NEXP * DMODEL * ESIZE];      // fp16 keys [e][d][h]
__device__ __half g_valuesH[(size_t)NEXP * ESIZE * DMODEL];    // fp16 values [e][h][v]
__device__ __half g_Hh[(size_t)NTOK * TOPK * ESIZE];           // fp16 H rows
__device__ __half g_Yph[(size_t)NTOK * TOPK * DMODEL];         // fp16 partial y

__device__ __forceinline__ uint32_t smem_u32(const void* p) {
    uint32_t a;
    asm("{ .reg .u64 t; cvta.to.shared.u64 t, %1; cvt.u32.u64 %0, t; }" : "=r"(a) : "l"(p));
    return a;
}
#define CP_ASYNC16(dst, src) \
    asm volatile("cp.async.cg.shared.global [%0], [%1], 16;" :: "r"(dst), "l"(src))
#define CP_COMMIT() asm volatile("cp.async.commit_group;" ::: "memory")
#define CP_WAIT2()  asm volatile("cp.async.wait_group 2;" ::: "memory")
// streaming (evict-first) global access
#define STCS32(ptr, v) \
    asm volatile("st.global.cs.b32 [%0], %1;" :: "l"(ptr), "r"(v))
#define LDCS128(r0, r1, r2, r3, ptr) \
    asm volatile("ld.global.cs.v4.u32 {%0,%1,%2,%3}, [%4];" \
                 : "=r"(r0), "=r"(r1), "=r"(r2), "=r"(r3) : "l"(ptr))
#define STCS128(ptr, r0, r1, r2, r3) \
    asm volatile("st.global.cs.v4.b32 [%0], {%1,%2,%3,%4};" \
                 :: "l"(ptr), "r"(r0), "r"(r1), "r"(r2), "r"(r3))

// ---------------- kernel 0: zero counts ----------------
__global__ void zero_counts_kernel() {
    if (threadIdx.x < NEXP) g_counts[threadIdx.x] = 0;
}

// ---------------- routing + x->fp16 (1 warp per token; R7-proven) ----------------
__global__ __launch_bounds__(256) void route_kernel(const float* __restrict__ x,
                                                    const float* __restrict__ esel) {
    const int gw   = blockIdx.x * 8 + (threadIdx.x >> 5);
    const int lane = threadIdx.x & 31;

    const float* xr = x + (size_t)gw * DMODEL;
    float4 xreg[8];
#pragma unroll
    for (int j = 0; j < 8; j++) xreg[j] = *(const float4*)(xr + lane * 4 + j * 128);

#pragma unroll
    for (int j = 0; j < 8; j++) {
        __half2 h0 = __floats2half2_rn(xreg[j].x, xreg[j].y);
        __half2 h1 = __floats2half2_rn(xreg[j].z, xreg[j].w);
        uint2 o; o.x = *(uint32_t*)&h0; o.y = *(uint32_t*)&h1;
        *(uint2*)(g_xh + (size_t)gw * DMODEL + lane * 4 + j * 128) = o;
    }

    float myv = -INFINITY;
#pragma unroll 1
    for (int e = 0; e < NEXP; e++) {
        const float* w = esel + (size_t)e * DMODEL;
        float acc = 0.f;
#pragma unroll
        for (int j = 0; j < 8; j++) {
            float4 wv = *(const float4*)(w + lane * 4 + j * 128);
            acc += xreg[j].x * wv.x + xreg[j].y * wv.y + xreg[j].z * wv.z + xreg[j].w * wv.w;
        }
#pragma unroll
        for (int off = 16; off; off >>= 1) acc += __shfl_xor_sync(0xffffffffu, acc, off);
        if (lane == e) myv = acc;
    }

    float v = myv;
#pragma unroll
    for (int k = 0; k < TOPK; k++) {
        float bv = v; int bi = lane;
#pragma unroll
        for (int off = 16; off; off >>= 1) {
            float ov = __shfl_xor_sync(0xffffffffu, bv, off);
            int   oi = __shfl_xor_sync(0xffffffffu, bi, off);
            if (ov > bv || (ov == bv && oi < bi)) { bv = ov; bi = oi; }
        }
        if (lane == 0) {
            float g = 1.f / (1.f + expf(-bv));
            g_gate[gw * TOPK + k] = g;
            int pos = atomicAdd(&g_counts[bi], 1);
            g_toklist[bi][pos] = gw * TOPK + k;
        }
        if (lane == bi) v = -INFINITY;
    }
}

// ---------------- elementwise f32 -> f16 convert ----------------
__global__ __launch_bounds__(256) void convert_h_kernel(const float* __restrict__ in,
                                                        __half* __restrict__ out) {
    const int idx = blockIdx.x * 256 + threadIdx.x;
    const float4* p = (const float4*)in;
    float4 a = p[idx * 2], b = p[idx * 2 + 1];
    __half2 h0 = __floats2half2_rn(a.x, a.y);
    __half2 h1 = __floats2half2_rn(a.z, a.w);
    __half2 h2 = __floats2half2_rn(b.x, b.y);
    __half2 h3 = __floats2half2_rn(b.z, b.w);
    uint4 o;
    o.x = *(uint32_t*)&h0; o.y = *(uint32_t*)&h1;
    o.z = *(uint32_t*)&h2; o.w = *(uint32_t*)&h3;
    ((uint4*)out)[idx] = o;
}

// ---------------- build compacted tile list (1 warp) ----------------
__global__ void build_tiles_kernel() {
    const int lane = threadIdx.x;
    int cnt = g_counts[lane];
    int nt  = (cnt + 63) >> 6;                // ceil(cnt/64), BM=64
    int off = nt;
#pragma unroll
    for (int d = 1; d < 32; d <<= 1) {
        int o = __shfl_up_sync(0xffffffffu, off, d);
        if (lane >= d) off += o;
    }
    int excl = off - nt;
    if (lane == 31) g_ntiles = off;
    for (int i = 0; i < nt; i++)
        g_tiles[excl + i] = (lane << 16) | i;
}

// ---------------- HMMA fp16 GEMM (R9/R11 core): BM=64, BN=256, BK=32, 8 warps ----
#define ASTRIDE 40    // halves per A smem row (80B)
#define BSTRIDE 264   // halves per B smem row (528B): conflict-free trans ldmatrix
#define NSTAGE  4
#define A_ST_BYTES (64 * ASTRIDE * 2)    // 5120
#define B_ST_BYTES (32 * BSTRIDE * 2)    // 16896
#define SM_OFF_A   1024
#define SM_OFF_B   (SM_OFF_A + NSTAGE * A_ST_BYTES)
#define SM_TOTAL   (SM_OFF_B + NSTAGE * B_ST_BYTES)   // 89088

__device__ __forceinline__ void ldsm_x4(uint32_t (&r)[4], uint32_t addr) {
    asm volatile("ldmatrix.sync.aligned.m8n8.x4.shared.b16 {%0,%1,%2,%3}, [%4];"
                 : "=r"(r[0]), "=r"(r[1]), "=r"(r[2]), "=r"(r[3]) : "r"(addr));
}
__device__ __forceinline__ void ldsm_x4_trans(uint32_t (&r)[4], uint32_t addr) {
    asm volatile("ldmatrix.sync.aligned.m8n8.x4.trans.shared.b16 {%0,%1,%2,%3}, [%4];"
                 : "=r"(r[0]), "=r"(r[1]), "=r"(r[2]), "=r"(r[3]) : "r"(addr));
}
__device__ __forceinline__ void mma16816(float (&c)[4], const uint32_t (&a)[4],
                                         uint32_t b0, uint32_t b1) {
    asm volatile(
        "mma.sync.aligned.m16n8k16.row.col.f32.f16.f16.f32 "
        "{%0,%1,%2,%3}, {%4,%5,%6,%7}, {%8,%9}, {%0,%1,%2,%3};"
        : "+f"(c[0]), "+f"(c[1]), "+f"(c[2]), "+f"(c[3])
        : "r"(a[0]), "r"(a[1]), "r"(a[2]), "r"(a[3]), "r"(b0), "r"(b1));
}

template <int KDIM, int N_LD, bool IS_G1>
__global__ __launch_bounds__(256, 2) void moe_hmma_kernel() {
    extern __shared__ char smem[];
    if (blockIdx.y >= (unsigned)g_ntiles) return;
    const int tile = g_tiles[blockIdx.y];
    const int e    = tile >> 16;
    const int m0   = (tile & 0xffff) * 64;
    const int cnt  = g_counts[e];
    const int n0   = blockIdx.x * 256;

    int*   sPacked = (int*)(smem);
    float* sGate   = (float*)(smem + 256);

    const int tid    = threadIdx.x;
    const int lane   = tid & 31;
    const int wid    = tid >> 5;
    const int warp_m = wid & 1;      // 0..1 -> 32 rows each
    const int warp_n = wid >> 1;     // 0..3 -> 64 cols each

    if (tid < 64) {
        int m = m0 + tid;
        int p = (m < cnt) ? g_toklist[e][m] : -1;
        sPacked[tid] = p;
        sGate[tid]   = (IS_G1 && p >= 0) ? g_gate[p] : 0.f;
    }
    __syncthreads();

    const int arow = tid >> 2;
    const int ac   = tid & 3;
    const int apk  = sPacked[arow];
    const __half* Arow = (apk >= 0)
        ? (IS_G1 ? (g_xh + (size_t)(apk >> 2) * KDIM) : (g_Hh + (size_t)apk * KDIM))
        : (IS_G1 ? g_xh : g_Hh);               // dummy valid row; epilogue skips
    const __half* Bsrc = (IS_G1 ? g_keysH : g_valuesH) + (size_t)e * KDIM * N_LD + n0;

    const uint32_t sb = smem_u32(smem);

    auto issue_stage = [&](int s) {
        const int st = s % NSTAGE;
        const int k0 = s * 32;
        uint32_t ad = sb + SM_OFF_A + st * A_ST_BYTES + arow * (ASTRIDE * 2);
        CP_ASYNC16(ad + ac * 16, Arow + k0 + ac * 8);
        uint32_t bd = sb + SM_OFF_B + st * B_ST_BYTES;
#pragma unroll
        for (int j = 0; j < 4; j++) {
            int idx = tid + 256 * j;
            int row = idx >> 5, c16 = idx & 31;
            CP_ASYNC16(bd + row * (BSTRIDE * 2) + c16 * 16,
                       Bsrc + (size_t)(k0 + row) * N_LD + c16 * 8);
        }
        CP_COMMIT();
    };

    const int S = KDIM / 32;
#pragma unroll
    for (int p = 0; p < NSTAGE - 1; p++) issue_stage(p);

    float c[2][8][4];
#pragma unroll
    for (int i = 0; i < 2; i++)
#pragma unroll
        for (int j = 0; j < 8; j++)
#pragma unroll
            for (int k = 0; k < 4; k++) c[i][j][k] = 0.f;

    const int lr = lane & 15;
    const int lh = (lane >> 4) * 8;

#pragma unroll 1
    for (int s = 0; s < S; s++) {
        CP_WAIT2();
        __syncthreads();
        if (s + NSTAGE - 1 < S) issue_stage(s + NSTAGE - 1);
        else CP_COMMIT();

        const int st = s % NSTAGE;
        const uint32_t sA = sb + SM_OFF_A + st * A_ST_BYTES;
        const uint32_t sB = sb + SM_OFF_B + st * B_ST_BYTES;
#pragma unroll
        for (int kk = 0; kk < 32; kk += 16) {
            uint32_t a[2][4];
#pragma unroll
            for (int mt = 0; mt < 2; mt++)
                ldsm_x4(a[mt], sA + ((warp_m * 32 + mt * 16 + lr) * ASTRIDE + kk + lh) * 2);
            uint32_t bt[4][4];
#pragma unroll
            for (int g = 0; g < 4; g++)
                ldsm_x4_trans(bt[g], sB + ((kk + lr) * BSTRIDE + warp_n * 64 + g * 16 + lh) * 2);
#pragma unroll
            for (int mt = 0; mt < 2; mt++)
#pragma unroll
                for (int nt = 0; nt < 8; nt++)
                    mma16816(c[mt][nt], a[mt],
                             bt[nt >> 1][2 * (nt & 1)], bt[nt >> 1][2 * (nt & 1) + 1]);
        }
        // no trailing sync: buffer reuse distance is NSTAGE-1 stages; the top
        // __syncthreads of the next iteration orders reads before the overwrite.
    }

    const int erow = lane >> 2;
    const int ecol = (lane & 3) * 2;
#pragma unroll
    for (int mt = 0; mt < 2; mt++) {
#pragma unroll
        for (int h = 0; h < 2; h++) {
            int ml = warp_m * 32 + mt * 16 + erow + h * 8;
            int packed = sPacked[ml];
            if (packed < 0) continue;
            if (IS_G1) {
                float gate = sGate[ml];
                __half* dst = g_Hh + (size_t)packed * ESIZE + n0 + warp_n * 64 + ecol;
#pragma unroll
                for (int nt = 0; nt < 8; nt++) {
                    float f0 = fmaxf(c[mt][nt][2 * h + 0], 0.f) * gate;
                    float f1 = fmaxf(c[mt][nt][2 * h + 1], 0.f) * gate;
                    *(__half2*)(dst + nt * 8) = __floats2half2_rn(f0, f1);
                }
            } else {
                __half* dst = g_Yph + (size_t)packed * DMODEL + n0 + warp_n * 64 + ecol;
#pragma unroll
                for (int nt = 0; nt < 8; nt++) {
                    __half2 hv = __floats2half2_rn(c[mt][nt][2 * h + 0],
                                                   c[mt][nt][2 * h + 1]);
                    STCS32(dst + nt * 8, *(uint32_t*)&hv);   // streaming: evict-first
                }
            }
        }
    }
}

// ---------------- reduce: y[t] = sum_slot Yph[t*4+slot] (fp32 accumulate) --------
__global__ __launch_bounds__(256) void reduce_kernel(float* __restrict__ y) {
    int idx = blockIdx.x * blockDim.x + threadIdx.x;
    if (idx >= NTOK * (DMODEL / 8)) return;
    int t  = idx >> 7;
    int d8 = idx & 127;
    float acc[8];
#pragma unroll
    for (int i = 0; i < 8; i++) acc[i] = 0.f;
#pragma unroll
    for (int sl = 0; sl < TOPK; sl++) {
        const __half* src = g_Yph + ((size_t)(t * TOPK + sl)) * DMODEL + d8 * 8;
        uint32_t r0, r1, r2, r3;
        LDCS128(r0, r1, r2, r3, src);
        uint32_t rr[4] = {r0, r1, r2, r3};
#pragma unroll
        for (int i = 0; i < 4; i++) {
            float2 f = __half22float2(*(__half2*)&rr[i]);
            acc[i * 2 + 0] += f.x;
            acc[i * 2 + 1] += f.y;
        }
    }
    float* out = y + (size_t)t * DMODEL + d8 * 8;
    STCS128(out,     __float_as_uint(acc[0]), __float_as_uint(acc[1]),
                     __float_as_uint(acc[2]), __float_as_uint(acc[3]));
    STCS128(out + 4, __float_as_uint(acc[4]), __float_as_uint(acc[5]),
                     __float_as_uint(acc[6]), __float_as_uint(acc[7]));
}

// ---------------- launch: fork/join DAG over 3 streams ----------------
extern "C" void kernel_launch(void* const* d_in, const int* in_sizes, int n_in,
                              void* d_out, int out_size) {
    const float* x      = (const float*)d_in[0];
    const float* keys   = (const float*)d_in[1];
    const float* values = (const float*)d_in[2];
    const float* esel   = (const float*)d_in[3];
    float*       y      = (float*)d_out;

    static cudaStream_t s2 = nullptr, s3 = nullptr;
    static cudaEvent_t evRoot = nullptr, evK = nullptr, evV = nullptr;
    static bool inited = false;
    if (!inited) {
        cudaStreamCreateWithFlags(&s2, cudaStreamNonBlocking);
        cudaStreamCreateWithFlags(&s3, cudaStreamNonBlocking);
        cudaEventCreateWithFlags(&evRoot, cudaEventDisableTiming);
        cudaEventCreateWithFlags(&evK,    cudaEventDisableTiming);
        cudaEventCreateWithFlags(&evV,    cudaEventDisableTiming);
        cudaFuncSetAttribute(moe_hmma_kernel<DMODEL, ESIZE, true>,
                             cudaFuncAttributeMaxDynamicSharedMemorySize, SM_TOTAL);
        cudaFuncSetAttribute(moe_hmma_kernel<ESIZE, DMODEL, false>,
                             cudaFuncAttributeMaxDynamicSharedMemorySize, SM_TOTAL);
        inited = true;
    }

    const int wn8blocks = NEXP * DMODEL * ESIZE / 8 / 256;   // 4096

    // fork
    zero_counts_kernel<<<1, 32>>>();
    cudaEventRecord(evRoot, 0);
    cudaStreamWaitEvent(s2, evRoot, 0);
    cudaStreamWaitEvent(s3, evRoot, 0);

    // main: route -> tiles ; s2: keys convert ; s3: values convert
    route_kernel<<<NTOK / 8, 256>>>(x, esel);
    build_tiles_kernel<<<1, 32>>>();

    __half* keysH_p;   cudaGetSymbolAddress((void**)&keysH_p, g_keysH);
    __half* valuesH_p; cudaGetSymbolAddress((void**)&valuesH_p, g_valuesH);
    convert_h_kernel<<<wn8blocks, 256, 0, s2>>>(keys,   keysH_p);
    convert_h_kernel<<<wn8blocks, 256, 0, s3>>>(values, valuesH_p);
    cudaEventRecord(evK, s2);
    cudaEventRecord(evV, s3);

    // join keys before GEMM1
    cudaStreamWaitEvent(0, evK, 0);
    dim3 g1(1, MAX_TILES, 1);
    moe_hmma_kernel<DMODEL, ESIZE, true><<<g1, 256, SM_TOTAL>>>();

    // join values before GEMM2
    cudaStreamWaitEvent(0, evV, 0);
    dim3 g2(4, MAX_TILES, 1);
    moe_hmma_kernel<ESIZE, DMODEL, false><<<g2, 256, SM_TOTAL>>>();

    reduce_kernel<<<(NTOK * (DMODEL / 8) + 255) / 256, 256>>>(y);
}